// round 8
// baseline (speedup 1.0000x reference)
#include <cuda_runtime.h>
#include <cuda_bf16.h>
#include <cstdint>

#define Bb   2
#define Nn   16384
#define Tt   2048
#define Dd   128
#define Ss   384
#define NWw  512
#define WQq  32
#define Hh   128
#define Ll   3
#define NHh  4
#define NTOKk 33
#define BN   (Bb*Nn)          // 32768
#define PL2  278528           // packed weight floats per layer (bf16 = 2x)

// ---------------- scratch (device globals; allocation-free) ----------------
__device__ __align__(256) float g_q   [BN*Dd];
__device__ __align__(256) __nv_bfloat16 g_cn [BN*256];     // ln(c) hi|lo
__device__ __align__(256) __nv_bfloat16 g_h  [BN*256];     // hcur hi|lo
__device__ __align__(256) __nv_bfloat16 g_t3 [BN*256];     // attn out hi|lo
__device__ __align__(256) float g_t1  [BN*256];            // glu out (bf16 view)
__device__ __align__(256) float g_t2  [(size_t)BN*512];    // Q|G|K|V
__device__ __align__(256) float g_cng [(size_t)BN*768];    // cn gates; also a_cvt
__device__ __align__(256) float g_aw  [Bb*Tt*Dd];
__device__ __align__(256) float g_sf  [Bb*Tt*Dd];
__device__ __align__(256) __nv_bfloat16 g_wp [2*(Ll*PL2 + 49152)];
__device__ int g_tok[BN];

__device__ __forceinline__ float sigf(float x){ return 1.f/(1.f + __expf(-x)); }

__device__ __forceinline__ uint32_t s2u(const void* p){
    uint32_t a;
    asm("{ .reg .u64 t; cvta.to.shared.u64 t, %1; cvt.u32.u64 %0, t; }" : "=r"(a) : "l"(p));
    return a;
}

// ---------------- bf16 mma.sync GEMM, tile 128x128, warp 32x64 -------------
// A[M,2K] bf16 hi|lo rows, Bt[N,2K] bf16 hi|lo rows.
// D = Ah@Bh + Ah@Bl + Al@Bh, fp32 register accumulate.
// K-chunk 32, 2-stage cp.async pipeline, 80KB smem -> 2 CTAs/SM.
// mode 0: C[M,N] fp32 store
// mode 1: qbuf[r,128] += sigmoid(gate[r,768-stride]) * acc   (N=128 GEMMs)
// mode 2: GLU epilogue (interleaved W1|W2 packing): writes silu(a)*b as
//         bf16 hi|lo into obf rows of 512 (hi at +64*bx, lo at +256+64*bx)
#define AS2   40
#define BUFB  (128*AS2*2)      // 10240
#define STG   (4*BUFB)         // 40960
#define GEMM_SMEM (2*STG)      // 81920

__device__ __forceinline__ void mma16816(float* d, const uint32_t* a,
                                         uint32_t b0, uint32_t b1){
    asm volatile(
        "mma.sync.aligned.m16n8k16.row.col.f32.bf16.bf16.f32 "
        "{%0,%1,%2,%3}, {%4,%5,%6,%7}, {%8,%9}, {%0,%1,%2,%3};"
        : "+f"(d[0]), "+f"(d[1]), "+f"(d[2]), "+f"(d[3])
        : "r"(a[0]), "r"(a[1]), "r"(a[2]), "r"(a[3]), "r"(b0), "r"(b1));
}
__device__ __forceinline__ void ldsm4(uint32_t* r, uint32_t a){
    asm volatile("ldmatrix.sync.aligned.m8n8.x4.shared.b16 {%0,%1,%2,%3}, [%4];"
        : "=r"(r[0]), "=r"(r[1]), "=r"(r[2]), "=r"(r[3]) : "r"(a));
}
__device__ __forceinline__ void cpa16(uint32_t d, const void* s){
    asm volatile("cp.async.cg.shared.global [%0], [%1], 16;" :: "r"(d), "l"(s));
}

__global__ __launch_bounds__(256, 2) void gemm_tc(
    const __nv_bfloat16* __restrict__ A, const __nv_bfloat16* __restrict__ Bt,
    float* __restrict__ C, int Ntot, int Ktot, int mode,
    const float* __restrict__ gate, float* __restrict__ qbuf,
    __nv_bfloat16* __restrict__ obf)
{
    extern __shared__ __nv_bfloat16 smb[];
    const uint32_t smbase = s2u(smb);
    const int tid = threadIdx.x, wid = tid >> 5, lane = tid & 31;
    const int m0 = blockIdx.y << 7, n0 = blockIdx.x << 7;

    // loaders: thread t -> 32 bf16 (64B) of one A row and one B row per chunk
    const int lr = tid & 127;
    const int isLo = tid >> 7;
    const __nv_bfloat16* srcA = A + (size_t)(m0 + lr)*(2*Ktot) + (isLo ? Ktot : 0);
    const __nv_bfloat16* srcB = Bt + (size_t)(n0 + lr)*(2*Ktot) + (isLo ? Ktot : 0);
    const uint32_t dA = (uint32_t)(isLo*BUFB + lr*(AS2*2));
    const uint32_t dB = (uint32_t)(2*BUFB + isLo*BUFB + lr*(AS2*2));

    const int wm = (wid & 3) << 5;     // 0,32,64,96
    const int wn = (wid >> 2) << 6;    // 0,64
    const uint32_t aoff =
        ((uint32_t)(wm + ((lane>>3)&1)*8 + (lane&7))*AS2 + (uint32_t)(lane>>4)*8)*2u;
    const uint32_t boff = 2u*BUFB +
        ((uint32_t)(wn + (lane>>4)*8 + (lane&7))*AS2 + (uint32_t)((lane>>3)&1)*8)*2u;

    float acc[2][8][4];
#pragma unroll
    for (int a = 0; a < 2; a++)
#pragma unroll
        for (int b = 0; b < 8; b++)
#pragma unroll
            for (int k = 0; k < 4; k++) acc[a][b][k] = 0.f;

    const int nch = Ktot >> 5;

    {
        uint32_t st = smbase;
#pragma unroll
        for (int i = 0; i < 4; i++) cpa16(st + dA + i*16, srcA + i*8);
#pragma unroll
        for (int i = 0; i < 4; i++) cpa16(st + dB + i*16, srcB + i*8);
        asm volatile("cp.async.commit_group;");
    }

    for (int c = 0; c < nch; c++) {
        if (c + 1 < nch) {
            uint32_t st = smbase + ((c+1)&1)*STG;
            const __nv_bfloat16* sa = srcA + ((c+1)<<5);
            const __nv_bfloat16* sb = srcB + ((c+1)<<5);
#pragma unroll
            for (int i = 0; i < 4; i++) cpa16(st + dA + i*16, sa + i*8);
#pragma unroll
            for (int i = 0; i < 4; i++) cpa16(st + dB + i*16, sb + i*8);
            asm volatile("cp.async.commit_group;");
            asm volatile("cp.async.wait_group 1;");
        } else {
            asm volatile("cp.async.wait_group 0;");
        }
        __syncthreads();
        const uint32_t st = smbase + (uint32_t)(c&1)*STG;
#pragma unroll
        for (int ks = 0; ks < 2; ks++) {
            const uint32_t k0b = (uint32_t)ks*32u;
            uint32_t ah[2][4], al[2][4];
            ldsm4(ah[0], st + aoff + k0b);
            ldsm4(ah[1], st + aoff + 1280u + k0b);
            ldsm4(al[0], st + BUFB + aoff + k0b);
            ldsm4(al[1], st + BUFB + aoff + 1280u + k0b);
#pragma unroll
            for (int p = 0; p < 4; p++) {
                uint32_t bh[4], bl[4];
                ldsm4(bh, st + boff + (uint32_t)p*1280u + k0b);
                ldsm4(bl, st + boff + BUFB + (uint32_t)p*1280u + k0b);
#pragma unroll
                for (int i = 0; i < 2; i++) {
                    float* d0 = acc[0][p*2 + i];
                    float* d1 = acc[1][p*2 + i];
                    mma16816(d0, ah[0], bh[i*2], bh[i*2+1]);
                    mma16816(d1, ah[1], bh[i*2], bh[i*2+1]);
                    mma16816(d0, ah[0], bl[i*2], bl[i*2+1]);
                    mma16816(d1, ah[1], bl[i*2], bl[i*2+1]);
                    mma16816(d0, al[0], bh[i*2], bh[i*2+1]);
                    mma16816(d1, al[1], bh[i*2], bh[i*2+1]);
                }
            }
        }
        __syncthreads();
    }

    const int lq = lane >> 2, l4 = (lane & 3) << 1;
    if (mode == 0) {
#pragma unroll
        for (int mt = 0; mt < 2; mt++) {
            int r = m0 + wm + mt*16 + lq;
            float* cp0 = C + (size_t)r*Ntot + n0 + wn + l4;
            float* cp1 = cp0 + (size_t)8*Ntot;
#pragma unroll
            for (int nt = 0; nt < 8; nt++) {
                *(float2*)(cp0 + nt*8) = make_float2(acc[mt][nt][0], acc[mt][nt][1]);
                *(float2*)(cp1 + nt*8) = make_float2(acc[mt][nt][2], acc[mt][nt][3]);
            }
        }
    } else if (mode == 1) {
        // q += sigmoid(gate) * acc   (Ntot==128, n0==0)
#pragma unroll
        for (int mt = 0; mt < 2; mt++) {
#pragma unroll
            for (int half = 0; half < 2; half++) {
                int r = m0 + wm + mt*16 + lq + half*8;
#pragma unroll
                for (int nt = 0; nt < 8; nt++) {
                    int col = wn + nt*8 + l4;
                    float2 g = *(const float2*)(gate + (size_t)r*768 + col);
                    float2 qv = *(float2*)(qbuf + (size_t)r*128 + col);
                    qv.x += sigf(g.x)*acc[mt][nt][half*2];
                    qv.y += sigf(g.y)*acc[mt][nt][half*2+1];
                    *(float2*)(qbuf + (size_t)r*128 + col) = qv;
                }
            }
        }
    } else {
        // GLU: tile holds W1 cols [0:64) and W2 cols [64:128) of group bx
        float* cbuf = (float*)smb;             // 128 x 132 fp32 = 67584 B
#pragma unroll
        for (int mt = 0; mt < 2; mt++) {
#pragma unroll
            for (int half = 0; half < 2; half++) {
                int rl = wm + mt*16 + lq + half*8;
#pragma unroll
                for (int nt = 0; nt < 8; nt++) {
                    int col = wn + nt*8 + l4;
                    *(float2*)(cbuf + rl*132 + col) =
                        make_float2(acc[mt][nt][half*2], acc[mt][nt][half*2+1]);
                }
            }
        }
        __syncthreads();
        const int gbase = (int)(blockIdx.x << 6);
#pragma unroll
        for (int i = 0; i < 32; i++) {
            int lin = tid + (i << 8);
            int cl = lin & 63, rw = lin >> 6;
            float a2 = cbuf[rw*132 + cl];
            float b2 = cbuf[rw*132 + cl + 64];
            float v = a2*sigf(a2)*b2;
            __nv_bfloat16 hi = __float2bfloat16(v);
            __nv_bfloat16 lo = __float2bfloat16(v - __bfloat162float(hi));
            size_t base = (size_t)(m0 + rw)*512 + gbase + cl;
            obf[base] = hi;
            obf[base + 256] = lo;
        }
    }
}

// ---------------- attention: one block per (head, window, batch) ------------
// qg: (BN, 512) fp32 = [Q | G | K | V]; K/V rows gathered via kidx.
__global__ __launch_bounds__(128) void attn_kernel(
    const float* __restrict__ qg, const float* __restrict__ bias,
    const float* __restrict__ mask, const int* __restrict__ kidx,
    __nv_bfloat16* __restrict__ obuf)
{
    __shared__ float qs[32*33];
    __shared__ float ks[128*33];
    __shared__ float sc[32*129];
    __shared__ float mv[128];
    __shared__ int   kid[128];
    const int t  = threadIdx.x;
    const int hd = blockIdx.x, w = blockIdx.y, b = blockIdx.z;
    const size_t qbase = ((size_t)(b*Nn + w*WQq))*512 + hd*32;

#pragma unroll
    for (int i = 0; i < 8; i++) {
        int s = t + i*128; int qq = s >> 5, d = s & 31;
        qs[qq*33 + d] = qg[qbase + (size_t)qq*512 + d];
    }
    {
        int ki = kidx[w*Hh + t];
        kid[t] = b*Nn + ki;
        mv[t] = (1.0f - mask[b*Nn + ki]) * -1e9f;
    }
    __syncthreads();

#pragma unroll
    for (int i = 0; i < 32; i++) {
        int s = t + i*128; int kk = s >> 5, d = s & 31;
        ks[kk*33 + d] = qg[(size_t)kid[kk]*512 + 256 + hd*32 + d];
    }
    __syncthreads();

    const float* bptr = bias + ((((size_t)b*NWw + w)*NHh + hd)*WQq)*Hh + t;
    const float mvt = mv[t];
#pragma unroll 4
    for (int qq = 0; qq < 32; qq++) {
        float a = 0.f;
#pragma unroll
        for (int d = 0; d < 32; d++) a += qs[qq*33 + d]*ks[t*33 + d];
        sc[qq*129 + t] = a*0.17677669529663689f + bptr[(size_t)qq*Hh] + mvt;
    }
    __syncthreads();

#pragma unroll
    for (int i = 0; i < 32; i++) {
        int s = t + i*128; int kk = s >> 5, d = s & 31;
        ks[kk*33 + d] = qg[(size_t)kid[kk]*512 + 384 + hd*32 + d];
    }
    {
        int qq = t >> 2, seg = t & 3;
        float* row = sc + qq*129 + seg*32;
        float mx = -1e30f;
#pragma unroll
        for (int j = 0; j < 32; j++) mx = fmaxf(mx, row[j]);
        mx = fmaxf(mx, __shfl_xor_sync(0xffffffffu, mx, 1));
        mx = fmaxf(mx, __shfl_xor_sync(0xffffffffu, mx, 2));
        float sum = 0.f;
#pragma unroll
        for (int j = 0; j < 32; j++) { float e = __expf(row[j]-mx); row[j] = e; sum += e; }
        sum += __shfl_xor_sync(0xffffffffu, sum, 1);
        sum += __shfl_xor_sync(0xffffffffu, sum, 2);
        float inv = 1.f/sum;
#pragma unroll
        for (int j = 0; j < 32; j++) row[j] *= inv;
    }
    __syncthreads();

    {
        int qq = t >> 2, ds = (t & 3) * 8;
        float acc[8];
#pragma unroll
        for (int j = 0; j < 8; j++) acc[j] = 0.f;
#pragma unroll 8
        for (int k = 0; k < 128; k++) {
            float s = sc[qq*129 + k];
#pragma unroll
            for (int j = 0; j < 8; j++) acc[j] += s*ks[k*33 + ds + j];
        }
        size_t nrow = (size_t)(b*Nn + w*WQq + qq);
        int col = hd*32 + ds;
        float v[8];
#pragma unroll
        for (int j = 0; j < 8; j++) {
            float g = qg[nrow*512 + 128 + col + j];
            v[j] = acc[j] * sigf(g);
        }
        uint32_t hi[4], lo[4];
#pragma unroll
        for (int j = 0; j < 4; j++) {
            __nv_bfloat162 h = __floats2bfloat162_rn(v[j*2], v[j*2+1]);
            float2 f = __bfloat1622float2(h);
            __nv_bfloat162 l = __floats2bfloat162_rn(v[j*2]-f.x, v[j*2+1]-f.y);
            hi[j] = *(uint32_t*)&h; lo[j] = *(uint32_t*)&l;
        }
        *(uint4*)(obuf + nrow*256 + col)       = make_uint4(hi[0],hi[1],hi[2],hi[3]);
        *(uint4*)(obuf + nrow*256 + 128 + col) = make_uint4(lo[0],lo[1],lo[2],lo[3]);
    }
}

// ---------------- elementwise / small kernels ----------------
__device__ __forceinline__ void store_hilo4(__nv_bfloat16* base, int off_lo,
                                            float a, float b, float c2, float d){
    __nv_bfloat162 h01 = __floats2bfloat162_rn(a, b);
    __nv_bfloat162 h23 = __floats2bfloat162_rn(c2, d);
    float2 f01 = __bfloat1622float2(h01);
    float2 f23 = __bfloat1622float2(h23);
    __nv_bfloat162 l01 = __floats2bfloat162_rn(a-f01.x, b-f01.y);
    __nv_bfloat162 l23 = __floats2bfloat162_rn(c2-f23.x, d-f23.y);
    *(uint2*)base = make_uint2(*(uint32_t*)&h01, *(uint32_t*)&h23);
    *(uint2*)(base + off_lo) = make_uint2(*(uint32_t*)&l01, *(uint32_t*)&l23);
}

__global__ void ln_rows(const float* __restrict__ x, __nv_bfloat16* __restrict__ y) {
    int warp = threadIdx.x >> 5, lane = threadIdx.x & 31;
    size_t row = (size_t)blockIdx.x*8 + warp;
    float4 v = *(const float4*)(x + row*128 + lane*4);
    float s  = v.x+v.y+v.z+v.w;
    float ss = v.x*v.x+v.y*v.y+v.z*v.z+v.w*v.w;
#pragma unroll
    for (int o = 16; o; o >>= 1) { s += __shfl_xor_sync(~0u, s, o); ss += __shfl_xor_sync(~0u, ss, o); }
    float m = s*(1.f/128.f);
    float rstd = rsqrtf(ss*(1.f/128.f) - m*m + 1e-5f);
    store_hilo4(y + row*256 + lane*4, 128,
                (v.x-m)*rstd, (v.y-m)*rstd, (v.z-m)*rstd, (v.w-m)*rstd);
}

__global__ void ew_hcur(const float* __restrict__ q, const float* __restrict__ X,
                        int xs, __nv_bfloat16* __restrict__ h) {
    int warp = threadIdx.x >> 5, lane = threadIdx.x & 31;
    size_t row = (size_t)blockIdx.x*8 + warp;
    float4 v = *(const float4*)(q + row*128 + lane*4);
    float s  = v.x+v.y+v.z+v.w;
    float ss = v.x*v.x+v.y*v.y+v.z*v.z+v.w*v.w;
#pragma unroll
    for (int o = 16; o; o >>= 1) { s += __shfl_xor_sync(~0u, s, o); ss += __shfl_xor_sync(~0u, ss, o); }
    float m = s*(1.f/128.f);
    float rstd = rsqrtf(ss*(1.f/128.f) - m*m + 1e-5f);
    float4 g  = *(const float4*)(X + row*xs + lane*4);
    float4 bb = *(const float4*)(X + row*xs + 128 + lane*4);
    store_hilo4(h + row*256 + lane*4, 128,
                (v.x-m)*rstd*sigf(g.x) + bb.x,
                (v.y-m)*rstd*sigf(g.y) + bb.y,
                (v.z-m)*rstd*sigf(g.z) + bb.z,
                (v.w-m)*rstd*sigf(g.w) + bb.w);
}

__global__ void cvt_hilo(const float* __restrict__ in, __nv_bfloat16* __restrict__ out,
                         int K, int total4) {
    int i4 = blockIdx.x*blockDim.x + threadIdx.x;
    if (i4 >= total4) return;
    int kq = K >> 2;
    size_t row = i4 / kq;
    int k4 = (i4 % kq) << 2;
    float4 v = *(const float4*)(in + row*K + k4);
    store_hilo4(out + row*(2*K) + k4, K, v.x, v.y, v.z, v.w);
}

__global__ void pack_all(
    const float* __restrict__ Wcs,  const float* __restrict__ Wcb,
    const float* __restrict__ Wog,  const float* __restrict__ Wcs2,
    const float* __restrict__ Wcb2, const float* __restrict__ Wog2,
    const float* __restrict__ Wq,   const float* __restrict__ Wg,
    const float* __restrict__ Wk,   const float* __restrict__ Wv,
    const float* __restrict__ W1,   const float* __restrict__ W2,
    const float* __restrict__ Wo,   const float* __restrict__ W3,
    const float* __restrict__ a2q,  __nv_bfloat16* __restrict__ dst)
{
    const int total = Ll*PL2 + 49152;
    for (int i = blockIdx.x*blockDim.x + threadIdx.x; i < total; i += gridDim.x*blockDim.x) {
        float v; size_t bb; int n, k, Km;
        if (i >= Ll*PL2) {                       // a2q^T : [128 rows, K=384]
            int r = i - Ll*PL2;
            n = r / 384; k = r % 384; Km = 384;
            bb = (size_t)Ll*2*PL2;
            v = a2q[k*128 + n];
        } else {
            int l = i / PL2, o = i % PL2;
            size_t lb = (size_t)l*2*PL2;
            if (o < 98304) {                     // 6 square mats [128,128]
                int m = o >> 14, r = o & 16383;
                n = r >> 7; k = r & 127; Km = 128;
                bb = lb + (size_t)m*32768;
                const float* S = (m==0)?Wcs:(m==1)?Wcb:(m==2)?Wog:(m==3)?Wcs2:(m==4)?Wcb2:Wog2;
                v = S[l*16384 + k*128 + n];
            } else if (o < 131072) {             // [Wq|Wg] : [256,128]
                int r = o - 98304;
                n = r >> 7; k = r & 127; Km = 128;
                bb = lb + 196608;
                v = (n < 128) ? Wq[l*16384 + k*128 + n] : Wg[l*16384 + k*128 + n-128];
            } else if (o < 163840) {             // [Wk|Wv] : [256,128]
                int r = o - 131072;
                n = r >> 7; k = r & 127; Km = 128;
                bb = lb + 262144;
                v = (n < 128) ? Wk[l*16384 + k*128 + n] : Wv[l*16384 + k*128 + n-128];
            } else if (o < 229376) {             // [W1|W2] interleaved 64-col groups
                int r = o - 163840;
                n = r >> 7; k = r & 127; Km = 128;
                bb = lb + 327680;
                int grp = n >> 7, within = n & 127;
                v = (within < 64) ? W1[l*32768 + k*256 + grp*64 + within]
                                  : W2[l*32768 + k*256 + grp*64 + within - 64];
            } else if (o < 245760) {             // Wo^T : [128,128]
                int r = o - 229376;
                n = r >> 7; k = r & 127; Km = 128;
                bb = lb + 458752;
                v = Wo[l*16384 + k*128 + n];
            } else {                             // W3^T : [128,256]
                int r = o - 245760;
                n = r >> 8; k = r & 255; Km = 256;
                bb = lb + 491520;
                v = W3[l*32768 + k*128 + n];
            }
        }
        __nv_bfloat16 hi = __float2bfloat16(v);
        __nv_bfloat16 lo = __float2bfloat16(v - __bfloat162float(hi));
        dst[bb + (size_t)n*2*Km + k]      = hi;
        dst[bb + (size_t)n*2*Km + Km + k] = lo;
    }
}

__global__ void argmax_tok(const float* __restrict__ a2t, int* __restrict__ tok) {
    int warp = threadIdx.x >> 5, lane = threadIdx.x & 31;
    size_t row = (size_t)blockIdx.x*8 + warp;
    const float* p = a2t + row*Tt;
    float bv = -1e30f; int bi = 0;
    for (int j = lane; j < Tt; j += 32) { float v = p[j]; if (v > bv) { bv = v; bi = j; } }
#pragma unroll
    for (int o = 16; o; o >>= 1) {
        float ov = __shfl_xor_sync(~0u, bv, o);
        int   oi = __shfl_xor_sync(~0u, bi, o);
        if (ov > bv || (ov == bv && oi < bi)) { bv = ov; bi = oi; }
    }
    if (lane == 0) tok[row] = bi;
}

__global__ void addaw_kernel(const float* __restrict__ qin, const float* __restrict__ aw,
                             const int* __restrict__ tok, float* __restrict__ q) {
    size_t i4 = (size_t)blockIdx.x*256 + threadIdx.x;
    int row = (int)(i4 >> 5);
    int d4  = (int)(i4 & 31) << 2;
    int b = row >> 14;
    int t = tok[row];
    float4 v = *(const float4*)(qin + ((size_t)row << 7) + d4);
    float4 w = *(const float4*)(aw + (((size_t)b*Tt + t) << 7) + d4);
    v.x += w.x; v.y += w.y; v.z += w.z; v.w += w.w;
    *(float4*)(q + ((size_t)row << 7) + d4) = v;
}

__global__ void sfeat_kernel(const float* __restrict__ q, const float* __restrict__ mask,
                             const int* __restrict__ tok, float* __restrict__ sf) {
    size_t e = (size_t)blockIdx.x*256 + threadIdx.x;
    int row = (int)(e >> 7);
    int d = (int)(e & 127);
    int b = row >> 14;
    int t = tok[row];
    atomicAdd(&sf[(((size_t)b*Tt + t) << 7) + d], q[e]*mask[row]);
}

__global__ __launch_bounds__(128) void restype_kernel(
    const float* __restrict__ sf, const float* __restrict__ Wres,
    const float* __restrict__ bres, float* __restrict__ out) {
    __shared__ float sr[128];
    int t = threadIdx.x;
    size_t row = blockIdx.x;
    sr[t] = sf[row*128 + t];
    __syncthreads();
    if (t < NTOKk) {
        float acc = bres[t];
#pragma unroll 16
        for (int d = 0; d < 128; d++) acc += sr[d]*Wres[d*NTOKk + t];
        out[row*NTOKk + t] = acc;
    }
}

__global__ __launch_bounds__(128) void rupdate_kernel(
    const float* __restrict__ q, const float* __restrict__ g,
    const float* __restrict__ bb, const float* __restrict__ Wpos,
    float* __restrict__ out) {
    __shared__ float r1[128], r2[128];
    __shared__ float ms, rs;
    int d = threadIdx.x;
    size_t row = blockIdx.x;
    float x = q[row*128 + d];
    r1[d] = x; r2[d] = x*x;
    __syncthreads();
    for (int o = 64; o; o >>= 1) { if (d < o) { r1[d] += r1[d+o]; r2[d] += r2[d+o]; } __syncthreads(); }
    if (d == 0) {
        float m = r1[0]*(1.f/128.f);
        float v = r2[0]*(1.f/128.f) - m*m;
        ms = m; rs = rsqrtf(v + 1e-5f);
    }
    __syncthreads();
    float y = (x - ms)*rs*g[d] + bb[d];
    float p0 = y*Wpos[d*3], p1 = y*Wpos[d*3+1], p2 = y*Wpos[d*3+2];
    r1[d] = p0; r2[d] = p1;
    __syncthreads();
    for (int o = 64; o; o >>= 1) { if (d < o) { r1[d] += r1[d+o]; r2[d] += r2[d+o]; } __syncthreads(); }
    if (d == 0) { out[row*3] = r1[0]; out[row*3+1] = r2[0]; }
    __syncthreads();
    r1[d] = p2;
    __syncthreads();
    for (int o = 64; o; o >>= 1) { if (d < o) { r1[d] += r1[d+o]; } __syncthreads(); }
    if (d == 0) out[row*3+2] = r1[0];
}

// ---------------- host launcher ----------------
extern "C" void kernel_launch(void* const* d_in, const int* in_sizes, int n_in,
                              void* d_out, int out_size) {
    (void)in_sizes; (void)n_in; (void)out_size;
    const float* a    = (const float*)d_in[0];
    const float* qin  = (const float*)d_in[1];
    const float* c    = (const float*)d_in[2];
    const float* bias = (const float*)d_in[3];
    const float* a2t  = (const float*)d_in[4];
    const float* mask = (const float*)d_in[5];
    const int*   kidx = (const int*)  d_in[6];
    const float* a2q  = (const float*)d_in[7];
    const float* Wq   = (const float*)d_in[8];
    const float* Wk   = (const float*)d_in[9];
    const float* Wv   = (const float*)d_in[10];
    const float* Wg   = (const float*)d_in[11];
    const float* Wo   = (const float*)d_in[12];
    const float* Wcs  = (const float*)d_in[13];
    const float* Wcb  = (const float*)d_in[14];
    const float* Wog  = (const float*)d_in[15];
    const float* Wcs2 = (const float*)d_in[16];
    const float* Wcb2 = (const float*)d_in[17];
    const float* Wog2 = (const float*)d_in[18];
    const float* W1   = (const float*)d_in[19];
    const float* W2   = (const float*)d_in[20];
    const float* W3   = (const float*)d_in[21];
    const float* ln_g = (const float*)d_in[22];
    const float* ln_b = (const float*)d_in[23];
    const float* Wpos = (const float*)d_in[24];
    const float* Wres = (const float*)d_in[25];
    const float* bres = (const float*)d_in[26];
    float* out = (float*)d_out;

    float *pq, *pt1, *pt2, *pcng, *paw, *psf;
    __nv_bfloat16 *pcn, *ph, *pt3, *pwp;
    int *ptok;
    cudaGetSymbolAddress((void**)&pq,   g_q);
    cudaGetSymbolAddress((void**)&pcn,  g_cn);
    cudaGetSymbolAddress((void**)&ph,   g_h);
    cudaGetSymbolAddress((void**)&pt1,  g_t1);
    cudaGetSymbolAddress((void**)&pt2,  g_t2);
    cudaGetSymbolAddress((void**)&pt3,  g_t3);
    cudaGetSymbolAddress((void**)&pcng, g_cng);
    cudaGetSymbolAddress((void**)&paw,  g_aw);
    cudaGetSymbolAddress((void**)&psf,  g_sf);
    cudaGetSymbolAddress((void**)&pwp,  g_wp);
    cudaGetSymbolAddress((void**)&ptok, g_tok);

    cudaFuncSetAttribute(gemm_tc, cudaFuncAttributeMaxDynamicSharedMemorySize, GEMM_SMEM);

    __nv_bfloat16* acvt = (__nv_bfloat16*)pcng;   // prologue-only bf16 view
    __nv_bfloat16* pglu = (__nv_bfloat16*)pt1;    // glu out (rows of 512 bf16)

    // prologue
    pack_all<<<512, 256>>>(Wcs, Wcb, Wog, Wcs2, Wcb2, Wog2, Wq, Wg, Wk, Wv,
                           W1, W2, Wo, W3, a2q, pwp);
    argmax_tok<<<BN/8, 256>>>(a2t, ptok);
    cvt_hilo<<<(Bb*Tt*Ss/4 + 255)/256, 256>>>(a, acvt, Ss, Bb*Tt*Ss/4);
    gemm_tc<<<dim3(1, (Bb*Tt)/128), 256, GEMM_SMEM>>>(acvt, pwp + (size_t)Ll*2*PL2,
        paw, 128, Ss, 0, nullptr, nullptr, nullptr);
    addaw_kernel<<<(BN*32)/256, 256>>>(qin, paw, ptok, pq);
    ln_rows<<<BN/8, 256>>>(c, pcn);

    for (int l = 0; l < Ll; l++) {
        __nv_bfloat16* wl = pwp + (size_t)l*2*PL2;
        // all six cn projections: [cs|cb|og|cs2|cb2|og2]
        gemm_tc<<<dim3(6, BN/128), 256, GEMM_SMEM>>>(pcn, wl, pcng, 768, Dd,
            0, nullptr, nullptr, nullptr);
        // hcur = ln(q)*sig(cs) + cb  -> bf16 hi|lo
        ew_hcur<<<BN/8, 256>>>(pq, pcng, 768, ph);
        // fused Q|G|K|V projection
        gemm_tc<<<dim3(4, BN/128), 256, GEMM_SMEM>>>(ph, wl + 196608, pt2, 512, Dd,
            0, nullptr, nullptr, nullptr);
        // attention (gathers K/V via kidx, sigmoid(G) gate) -> bf16 hi|lo
        attn_kernel<<<dim3(NHh, NWw, Bb), 128>>>(pt2, bias, mask, kidx, pt3);
        // q += sig(og) * (o@Wo)   [fused epilogue]
        gemm_tc<<<dim3(1, BN/128), 256, GEMM_SMEM>>>(pt3, wl + 458752, nullptr,
            128, Dd, 1, pcng + 256, pq, nullptr);
        // h2 = ln(q)*sig(cs2) + cb2 -> bf16 hi|lo
        ew_hcur<<<BN/8, 256>>>(pq, pcng + 384, 768, ph);
        // FFN up + GLU fused epilogue -> bf16 hi|lo
        gemm_tc<<<dim3(4, BN/128), 256, GEMM_SMEM>>>(ph, wl + 327680, nullptr,
            512, Dd, 2, nullptr, nullptr, pglu);
        // q += sig(og2) * (glu@W3)   [fused epilogue]
        gemm_tc<<<dim3(1, BN/128), 256, GEMM_SMEM>>>(pglu, wl + 491520, nullptr,
            128, 256, 1, pcng + 640, pq, nullptr);
    }

    // epilogue
    cudaMemsetAsync(psf, 0, (size_t)Bb*Tt*Dd*sizeof(float));
    sfeat_kernel<<<(BN*128)/256, 256>>>(pq, mask, ptok, psf);
    restype_kernel<<<Bb*Tt, 128>>>(psf, Wres, bres, out + (size_t)BN*3);
    rupdate_kernel<<<BN, 128>>>(pq, ln_g, ln_b, Wpos, out);
}

// round 9
// speedup vs baseline: 1.4776x; 1.4776x over previous
#include <cuda_runtime.h>
#include <cuda_fp16.h>
#include <cstdint>

#define Bb   2
#define Nn   16384
#define Tt   2048
#define Dd   128
#define Ss   384
#define NWw  512
#define WQq  32
#define Hh   128
#define Ll   3
#define NHh  4
#define NTOKk 33
#define BN   (Bb*Nn)          // 32768
#define PL1  278528           // packed weight halves per layer

// ---------------- scratch (device globals; allocation-free) ----------------
__device__ __align__(256) float g_q   [BN*Dd];
__device__ __align__(256) __half g_cn [BN*256];     // ln(c) hi|lo fp16
__device__ __align__(256) __half g_h  [BN*256];     // hcur hi|lo
__device__ __align__(256) __half g_t3 [BN*256];     // attn out hi|lo
__device__ __align__(256) float g_t1  [BN*256];     // Wo out / glu out (half view)
__device__ __align__(256) float g_t2  [(size_t)BN*512];    // Q|G|K|V
__device__ __align__(256) float g_kv  [(size_t)BN*512];    // FFN intermediate
__device__ __align__(256) float g_cng [(size_t)BN*768];    // cn gates; also a_cvt
__device__ __align__(256) float g_aw  [Bb*Tt*Dd];
__device__ __align__(256) float g_sf  [Bb*Tt*Dd];
__device__ __align__(256) __half g_wp [Ll*PL1 + 49152];
__device__ int g_tok[BN];

__device__ __forceinline__ float sigf(float x){ return 1.f/(1.f + __expf(-x)); }

__device__ __forceinline__ uint32_t s2u(const void* p){
    uint32_t a;
    asm("{ .reg .u64 t; cvta.to.shared.u64 t, %1; cvt.u32.u64 %0, t; }" : "=r"(a) : "l"(p));
    return a;
}

// ---------------- fp16 mma.sync GEMM, tile 128x128, warp 32x64 -------------
// A[M,2K] fp16 (hi rows | lo rows), B[N,K] fp16 (hi only), C[M,N] fp32.
// D = (Ah + Al) @ Bh, fp32 register accumulate. Dropped term ~2^-12 rel.
// K-chunk 32, 3-stage cp.async pipeline, 90KB smem -> 2 CTAs/SM.
// Stage layout: Ah@0, Al@BUFB, Bh@2*BUFB (row stride 40 halves)
#define AS2   40
#define BUFB  (128*AS2*2)      // 10240 bytes
#define STG   (3*BUFB)         // 30720
#define GEMM_SMEM (3*STG)      // 92160

__device__ __forceinline__ void mma16816(float* d, const uint32_t* a,
                                         uint32_t b0, uint32_t b1){
    asm volatile(
        "mma.sync.aligned.m16n8k16.row.col.f32.f16.f16.f32 "
        "{%0,%1,%2,%3}, {%4,%5,%6,%7}, {%8,%9}, {%0,%1,%2,%3};"
        : "+f"(d[0]), "+f"(d[1]), "+f"(d[2]), "+f"(d[3])
        : "r"(a[0]), "r"(a[1]), "r"(a[2]), "r"(a[3]), "r"(b0), "r"(b1));
}
__device__ __forceinline__ void ldsm4(uint32_t* r, uint32_t a){
    asm volatile("ldmatrix.sync.aligned.m8n8.x4.shared.b16 {%0,%1,%2,%3}, [%4];"
        : "=r"(r[0]), "=r"(r[1]), "=r"(r[2]), "=r"(r[3]) : "r"(a));
}
__device__ __forceinline__ void cpa16(uint32_t d, const void* s){
    asm volatile("cp.async.cg.shared.global [%0], [%1], 16;" :: "r"(d), "l"(s));
}

__global__ __launch_bounds__(256, 2) void gemm_tc(
    const __half* __restrict__ A, const __half* __restrict__ Bt,
    float* __restrict__ C, int Ntot, int Ktot)
{
    extern __shared__ __half smb[];
    const uint32_t smbase = s2u(smb);
    const int tid = threadIdx.x, wid = tid >> 5, lane = tid & 31;
    const int m0 = blockIdx.y << 7, n0 = blockIdx.x << 7;

    // loaders: all threads load 64B of A (hi or lo); threads 0-127 also load B
    const int lr = tid & 127;
    const int isLo = tid >> 7;
    const __half* srcA = A + (size_t)(m0 + lr)*(2*Ktot) + (isLo ? Ktot : 0);
    const __half* srcB = Bt + (size_t)(n0 + lr)*Ktot;
    const uint32_t dA = (uint32_t)(isLo*BUFB + lr*(AS2*2));
    const uint32_t dB = (uint32_t)(2*BUFB + lr*(AS2*2));

    const int wm = (wid & 3) << 5;     // 0,32,64,96
    const int wn = (wid >> 2) << 6;    // 0,64
    const uint32_t aoff =
        ((uint32_t)(wm + ((lane>>3)&1)*8 + (lane&7))*AS2 + (uint32_t)(lane>>4)*8)*2u;
    const uint32_t boff = 2u*BUFB +
        ((uint32_t)(wn + (lane>>4)*8 + (lane&7))*AS2 + (uint32_t)((lane>>3)&1)*8)*2u;

    float acc[2][8][4];
#pragma unroll
    for (int a = 0; a < 2; a++)
#pragma unroll
        for (int b = 0; b < 8; b++)
#pragma unroll
            for (int k = 0; k < 4; k++) acc[a][b][k] = 0.f;

    const int nch = Ktot >> 5;

    // prologue: issue up to 2 chunks
#pragma unroll
    for (int pc = 0; pc < 2; pc++) {
        if (pc < nch) {
            uint32_t st = smbase + (uint32_t)pc*STG;
            const __half* sa = srcA + (pc<<5);
#pragma unroll
            for (int i = 0; i < 4; i++) cpa16(st + dA + i*16, sa + i*8);
            if (tid < 128) {
                const __half* sb = srcB + (pc<<5);
#pragma unroll
                for (int i = 0; i < 4; i++) cpa16(st + dB + i*16, sb + i*8);
            }
            asm volatile("cp.async.commit_group;");
        }
    }

    for (int c = 0; c < nch; c++) {
        if (c + 2 < nch) {
            uint32_t st = smbase + (uint32_t)((c+2)%3)*STG;
            const __half* sa = srcA + ((c+2)<<5);
#pragma unroll
            for (int i = 0; i < 4; i++) cpa16(st + dA + i*16, sa + i*8);
            if (tid < 128) {
                const __half* sb = srcB + ((c+2)<<5);
#pragma unroll
                for (int i = 0; i < 4; i++) cpa16(st + dB + i*16, sb + i*8);
            }
            asm volatile("cp.async.commit_group;");
            asm volatile("cp.async.wait_group 2;");
        } else if (c + 1 < nch) {
            asm volatile("cp.async.wait_group 1;");
        } else {
            asm volatile("cp.async.wait_group 0;");
        }
        __syncthreads();
        const uint32_t st = smbase + (uint32_t)(c%3)*STG;
#pragma unroll
        for (int ks = 0; ks < 2; ks++) {
            const uint32_t k0b = (uint32_t)ks*32u;
            uint32_t ah[2][4], al[2][4];
            ldsm4(ah[0], st + aoff + k0b);
            ldsm4(ah[1], st + aoff + 1280u + k0b);
            ldsm4(al[0], st + BUFB + aoff + k0b);
            ldsm4(al[1], st + BUFB + aoff + 1280u + k0b);
#pragma unroll
            for (int p = 0; p < 4; p++) {
                uint32_t bh[4];
                ldsm4(bh, st + boff + (uint32_t)p*1280u + k0b);
#pragma unroll
                for (int i = 0; i < 2; i++) {
                    float* d0 = acc[0][p*2 + i];
                    float* d1 = acc[1][p*2 + i];
                    mma16816(d0, ah[0], bh[i*2], bh[i*2+1]);
                    mma16816(d1, ah[1], bh[i*2], bh[i*2+1]);
                    mma16816(d0, al[0], bh[i*2], bh[i*2+1]);
                    mma16816(d1, al[1], bh[i*2], bh[i*2+1]);
                }
            }
        }
        __syncthreads();
    }

    // epilogue
    const int lq = lane >> 2, l4 = (lane & 3) << 1;
#pragma unroll
    for (int mt = 0; mt < 2; mt++) {
        int r = m0 + wm + mt*16 + lq;
        float* cp0 = C + (size_t)r*Ntot + n0 + wn + l4;
        float* cp1 = cp0 + (size_t)8*Ntot;
#pragma unroll
        for (int nt = 0; nt < 8; nt++) {
            *(float2*)(cp0 + nt*8) = make_float2(acc[mt][nt][0], acc[mt][nt][1]);
            *(float2*)(cp1 + nt*8) = make_float2(acc[mt][nt][2], acc[mt][nt][3]);
        }
    }
}

// ---------------- attention: one block per (head, window, batch) ------------
// qg: (BN, 512) fp32 = [Q | G | K | V]; K/V rows gathered via kidx.
__global__ __launch_bounds__(128) void attn_kernel(
    const float* __restrict__ qg, const float* __restrict__ bias,
    const float* __restrict__ mask, const int* __restrict__ kidx,
    __half* __restrict__ obuf)
{
    __shared__ float qs[32*33];
    __shared__ float kvs[128*40];     // K phase: stride 33; V phase: stride 40
    __shared__ float sc[32*129];
    __shared__ float mv[128];
    __shared__ int   kid[128];
    const int t  = threadIdx.x;
    const int hd = blockIdx.x, w = blockIdx.y, b = blockIdx.z;
    const size_t qbase = ((size_t)(b*Nn + w*WQq))*512 + hd*32;

#pragma unroll
    for (int i = 0; i < 8; i++) {
        int s = t + i*128; int qq = s >> 5, d = s & 31;
        qs[qq*33 + d] = qg[qbase + (size_t)qq*512 + d];
    }
    {
        int ki = kidx[w*Hh + t];
        kid[t] = b*Nn + ki;
        mv[t] = (1.0f - mask[b*Nn + ki]) * -1e9f;
    }
    __syncthreads();

    // gathered K (col 256), stride 33 (conflict-free for scores phase)
#pragma unroll
    for (int i = 0; i < 32; i++) {
        int s = t + i*128; int kk = s >> 5, d = s & 31;
        kvs[kk*33 + d] = qg[(size_t)kid[kk]*512 + 256 + hd*32 + d];
    }
    __syncthreads();

    const float* bptr = bias + ((((size_t)b*NWw + w)*NHh + hd)*WQq)*Hh + t;
    const float mvt = mv[t];
#pragma unroll 4
    for (int qq = 0; qq < 32; qq++) {
        float a = 0.f;
#pragma unroll
        for (int d = 0; d < 32; d++) a += qs[qq*33 + d]*kvs[t*33 + d];
        sc[qq*129 + t] = a*0.17677669529663689f + bptr[(size_t)qq*Hh] + mvt;
    }
    __syncthreads();

    // gathered V (col 384) at stride 40 (float4-friendly) while softmax runs
#pragma unroll
    for (int i = 0; i < 8; i++) {
        int s = t + i*128; int kk = s >> 3, d4 = (s & 7) << 2;
        *(float4*)&kvs[kk*40 + d4] =
            *(const float4*)&qg[(size_t)kid[kk]*512 + 384 + hd*32 + d4];
    }
    {
        int qq = t >> 2, seg = t & 3;
        float* row = sc + qq*129 + seg*32;
        float mx = -1e30f;
#pragma unroll
        for (int j = 0; j < 32; j++) mx = fmaxf(mx, row[j]);
        mx = fmaxf(mx, __shfl_xor_sync(0xffffffffu, mx, 1));
        mx = fmaxf(mx, __shfl_xor_sync(0xffffffffu, mx, 2));
        float sum = 0.f;
#pragma unroll
        for (int j = 0; j < 32; j++) { float e = __expf(row[j]-mx); row[j] = e; sum += e; }
        sum += __shfl_xor_sync(0xffffffffu, sum, 1);
        sum += __shfl_xor_sync(0xffffffffu, sum, 2);
        float inv = 1.f/sum;
#pragma unroll
        for (int j = 0; j < 32; j++) row[j] *= inv;
    }
    __syncthreads();

    {
        int qq = t >> 2, ds = (t & 3) * 8;
        float acc[8];
#pragma unroll
        for (int j = 0; j < 8; j++) acc[j] = 0.f;
#pragma unroll 8
        for (int k = 0; k < 128; k++) {
            float s = sc[qq*129 + k];
            float4 v0 = *(const float4*)&kvs[k*40 + ds];
            float4 v1 = *(const float4*)&kvs[k*40 + ds + 4];
            acc[0] += s*v0.x; acc[1] += s*v0.y; acc[2] += s*v0.z; acc[3] += s*v0.w;
            acc[4] += s*v1.x; acc[5] += s*v1.y; acc[6] += s*v1.z; acc[7] += s*v1.w;
        }
        size_t nrow = (size_t)(b*Nn + w*WQq + qq);
        int col = hd*32 + ds;
        float v[8];
#pragma unroll
        for (int j = 0; j < 8; j++) {
            float g = qg[nrow*512 + 128 + col + j];
            v[j] = acc[j] * sigf(g);
        }
        uint32_t hi[4], lo[4];
#pragma unroll
        for (int j = 0; j < 4; j++) {
            __half2 h = __floats2half2_rn(v[j*2], v[j*2+1]);
            float2 f = __half22float2(h);
            __half2 l = __floats2half2_rn(v[j*2]-f.x, v[j*2+1]-f.y);
            hi[j] = *(uint32_t*)&h; lo[j] = *(uint32_t*)&l;
        }
        *(uint4*)(obuf + nrow*256 + col)       = make_uint4(hi[0],hi[1],hi[2],hi[3]);
        *(uint4*)(obuf + nrow*256 + 128 + col) = make_uint4(lo[0],lo[1],lo[2],lo[3]);
    }
}

// ---------------- elementwise / small kernels ----------------
__device__ __forceinline__ void store_hilo4(__half* base, int off_lo,
                                            float a, float b, float c2, float d){
    __half2 h01 = __floats2half2_rn(a, b);
    __half2 h23 = __floats2half2_rn(c2, d);
    float2 f01 = __half22float2(h01);
    float2 f23 = __half22float2(h23);
    __half2 l01 = __floats2half2_rn(a-f01.x, b-f01.y);
    __half2 l23 = __floats2half2_rn(c2-f23.x, d-f23.y);
    *(uint2*)base = make_uint2(*(uint32_t*)&h01, *(uint32_t*)&h23);
    *(uint2*)(base + off_lo) = make_uint2(*(uint32_t*)&l01, *(uint32_t*)&l23);
}

__global__ void ln_rows(const float* __restrict__ x, __half* __restrict__ y) {
    int warp = threadIdx.x >> 5, lane = threadIdx.x & 31;
    size_t row = (size_t)blockIdx.x*8 + warp;
    float4 v = *(const float4*)(x + row*128 + lane*4);
    float s  = v.x+v.y+v.z+v.w;
    float ss = v.x*v.x+v.y*v.y+v.z*v.z+v.w*v.w;
#pragma unroll
    for (int o = 16; o; o >>= 1) { s += __shfl_xor_sync(~0u, s, o); ss += __shfl_xor_sync(~0u, ss, o); }
    float m = s*(1.f/128.f);
    float rstd = rsqrtf(ss*(1.f/128.f) - m*m + 1e-5f);
    store_hilo4(y + row*256 + lane*4, 128,
                (v.x-m)*rstd, (v.y-m)*rstd, (v.z-m)*rstd, (v.w-m)*rstd);
}

__global__ void ew_hcur(const float* __restrict__ q, const float* __restrict__ X,
                        int xs, __half* __restrict__ h) {
    int warp = threadIdx.x >> 5, lane = threadIdx.x & 31;
    size_t row = (size_t)blockIdx.x*8 + warp;
    float4 v = *(const float4*)(q + row*128 + lane*4);
    float s  = v.x+v.y+v.z+v.w;
    float ss = v.x*v.x+v.y*v.y+v.z*v.z+v.w*v.w;
#pragma unroll
    for (int o = 16; o; o >>= 1) { s += __shfl_xor_sync(~0u, s, o); ss += __shfl_xor_sync(~0u, ss, o); }
    float m = s*(1.f/128.f);
    float rstd = rsqrtf(ss*(1.f/128.f) - m*m + 1e-5f);
    float4 g  = *(const float4*)(X + row*xs + lane*4);
    float4 bb = *(const float4*)(X + row*xs + 128 + lane*4);
    store_hilo4(h + row*256 + lane*4, 128,
                (v.x-m)*rstd*sigf(g.x) + bb.x,
                (v.y-m)*rstd*sigf(g.y) + bb.y,
                (v.z-m)*rstd*sigf(g.z) + bb.z,
                (v.w-m)*rstd*sigf(g.w) + bb.w);
}

__global__ void ew_resid(float* __restrict__ q, const float* __restrict__ gate,
                         int gs, const float* __restrict__ x) {
    size_t i4 = (size_t)blockIdx.x*blockDim.x + threadIdx.x;   // BN*32
    size_t row = i4 >> 5;
    int c4 = (int)(i4 & 31) << 2;
    float4 qq = *(float4*)(q + i4*4);
    float4 g  = *(const float4*)(gate + row*gs + c4);
    float4 xx = *(const float4*)(x + i4*4);
    qq.x += sigf(g.x)*xx.x; qq.y += sigf(g.y)*xx.y;
    qq.z += sigf(g.z)*xx.z; qq.w += sigf(g.w)*xx.w;
    *(float4*)(q + i4*4) = qq;
}

__global__ void ew_glu(const float* __restrict__ T, __half* __restrict__ out) {
    size_t i4 = (size_t)blockIdx.x*blockDim.x + threadIdx.x;   // BN*64
    size_t row = i4 >> 6;
    int c4 = (int)(i4 & 63) << 2;
    float4 a  = *(const float4*)(T + row*512 + c4);
    float4 bb = *(const float4*)(T + row*512 + 256 + c4);
    store_hilo4(out + row*512 + c4, 256,
                a.x*sigf(a.x)*bb.x, a.y*sigf(a.y)*bb.y,
                a.z*sigf(a.z)*bb.z, a.w*sigf(a.w)*bb.w);
}

__global__ void cvt_hilo(const float* __restrict__ in, __half* __restrict__ out,
                         int K, int total4) {
    int i4 = blockIdx.x*blockDim.x + threadIdx.x;
    if (i4 >= total4) return;
    int kq = K >> 2;
    size_t row = i4 / kq;
    int k4 = (i4 % kq) << 2;
    float4 v = *(const float4*)(in + row*K + k4);
    store_hilo4(out + row*(2*K) + k4, K, v.x, v.y, v.z, v.w);
}

// one-shot transpose-pack of all weights into single-fp16 [N,K] layout
__global__ void pack_all(
    const float* __restrict__ Wcs,  const float* __restrict__ Wcb,
    const float* __restrict__ Wog,  const float* __restrict__ Wcs2,
    const float* __restrict__ Wcb2, const float* __restrict__ Wog2,
    const float* __restrict__ Wq,   const float* __restrict__ Wg,
    const float* __restrict__ Wk,   const float* __restrict__ Wv,
    const float* __restrict__ W1,   const float* __restrict__ W2,
    const float* __restrict__ Wo,   const float* __restrict__ W3,
    const float* __restrict__ a2q,  __half* __restrict__ dst)
{
    const int total = Ll*PL1 + 49152;
    for (int i = blockIdx.x*blockDim.x + threadIdx.x; i < total; i += gridDim.x*blockDim.x) {
        float v; size_t bb; int n, k, Km;
        if (i >= Ll*PL1) {                       // a2q^T : [128, 384]
            int r = i - Ll*PL1;
            n = r / 384; k = r % 384; Km = 384;
            bb = (size_t)Ll*PL1;
            v = a2q[k*128 + n];
        } else {
            int l = i / PL1, o = i % PL1;
            size_t lb = (size_t)l*PL1;
            if (o < 98304) {                     // 6 square mats [128,128]
                int m = o >> 14, r = o & 16383;
                n = r >> 7; k = r & 127; Km = 128;
                bb = lb + (size_t)m*16384;
                const float* S = (m==0)?Wcs:(m==1)?Wcb:(m==2)?Wog:(m==3)?Wcs2:(m==4)?Wcb2:Wog2;
                v = S[l*16384 + k*128 + n];
            } else if (o < 163840) {             // [Wq|Wg|Wk|Wv] : [512,128]
                int r = o - 98304;
                n = r >> 7; k = r & 127; Km = 128;
                bb = lb + 98304;
                int m = n >> 7, nn = n & 127;
                const float* S = (m==0)?Wq:(m==1)?Wg:(m==2)?Wk:Wv;
                v = S[l*16384 + k*128 + nn];
            } else if (o < 229376) {             // [W1|W2] : [512,128]
                int r = o - 163840;
                n = r >> 7; k = r & 127; Km = 128;
                bb = lb + 163840;
                v = (n < 256) ? W1[l*32768 + k*256 + n] : W2[l*32768 + k*256 + n-256];
            } else if (o < 245760) {             // Wo^T : [128,128]
                int r = o - 229376;
                n = r >> 7; k = r & 127; Km = 128;
                bb = lb + 229376;
                v = Wo[l*16384 + k*128 + n];
            } else {                             // W3^T : [128,256]
                int r = o - 245760;
                n = r >> 8; k = r & 255; Km = 256;
                bb = lb + 245760;
                v = W3[l*32768 + k*128 + n];
            }
        }
        dst[bb + (size_t)n*Km + k] = __float2half(v);
    }
}

__global__ void argmax_tok(const float* __restrict__ a2t, int* __restrict__ tok) {
    int warp = threadIdx.x >> 5, lane = threadIdx.x & 31;
    size_t row = (size_t)blockIdx.x*8 + warp;
    const float* p = a2t + row*Tt;
    float bv = -1e30f; int bi = 0;
    for (int j = lane; j < Tt; j += 32) { float v = p[j]; if (v > bv) { bv = v; bi = j; } }
#pragma unroll
    for (int o = 16; o; o >>= 1) {
        float ov = __shfl_xor_sync(~0u, bv, o);
        int   oi = __shfl_xor_sync(~0u, bi, o);
        if (ov > bv || (ov == bv && oi < bi)) { bv = ov; bi = oi; }
    }
    if (lane == 0) tok[row] = bi;
}

__global__ void addaw_kernel(const float* __restrict__ qin, const float* __restrict__ aw,
                             const int* __restrict__ tok, float* __restrict__ q) {
    size_t i4 = (size_t)blockIdx.x*256 + threadIdx.x;
    int row = (int)(i4 >> 5);
    int d4  = (int)(i4 & 31) << 2;
    int b = row >> 14;
    int t = tok[row];
    float4 v = *(const float4*)(qin + ((size_t)row << 7) + d4);
    float4 w = *(const float4*)(aw + (((size_t)b*Tt + t) << 7) + d4);
    v.x += w.x; v.y += w.y; v.z += w.z; v.w += w.w;
    *(float4*)(q + ((size_t)row << 7) + d4) = v;
}

__global__ void sfeat_kernel(const float* __restrict__ q, const float* __restrict__ mask,
                             const int* __restrict__ tok, float* __restrict__ sf) {
    size_t e = (size_t)blockIdx.x*256 + threadIdx.x;
    int row = (int)(e >> 7);
    int d = (int)(e & 127);
    int b = row >> 14;
    int t = tok[row];
    atomicAdd(&sf[(((size_t)b*Tt + t) << 7) + d], q[e]*mask[row]);
}

__global__ __launch_bounds__(128) void restype_kernel(
    const float* __restrict__ sf, const float* __restrict__ Wres,
    const float* __restrict__ bres, float* __restrict__ out) {
    __shared__ float sr[128];
    int t = threadIdx.x;
    size_t row = blockIdx.x;
    sr[t] = sf[row*128 + t];
    __syncthreads();
    if (t < NTOKk) {
        float acc = bres[t];
#pragma unroll 16
        for (int d = 0; d < 128; d++) acc += sr[d]*Wres[d*NTOKk + t];
        out[row*NTOKk + t] = acc;
    }
}

__global__ __launch_bounds__(128) void rupdate_kernel(
    const float* __restrict__ q, const float* __restrict__ g,
    const float* __restrict__ bb, const float* __restrict__ Wpos,
    float* __restrict__ out) {
    __shared__ float r1[128], r2[128];
    __shared__ float ms, rs;
    int d = threadIdx.x;
    size_t row = blockIdx.x;
    float x = q[row*128 + d];
    r1[d] = x; r2[d] = x*x;
    __syncthreads();
    for (int o = 64; o; o >>= 1) { if (d < o) { r1[d] += r1[d+o]; r2[d] += r2[d+o]; } __syncthreads(); }
    if (d == 0) {
        float m = r1[0]*(1.f/128.f);
        float v = r2[0]*(1.f/128.f) - m*m;
        ms = m; rs = rsqrtf(v + 1e-5f);
    }
    __syncthreads();
    float y = (x - ms)*rs*g[d] + bb[d];
    float p0 = y*Wpos[d*3], p1 = y*Wpos[d*3+1], p2 = y*Wpos[d*3+2];
    r1[d] = p0; r2[d] = p1;
    __syncthreads();
    for (int o = 64; o; o >>= 1) { if (d < o) { r1[d] += r1[d+o]; r2[d] += r2[d+o]; } __syncthreads(); }
    if (d == 0) { out[row*3] = r1[0]; out[row*3+1] = r2[0]; }
    __syncthreads();
    r1[d] = p2;
    __syncthreads();
    for (int o = 64; o; o >>= 1) { if (d < o) { r1[d] += r1[d+o]; } __syncthreads(); }
    if (d == 0) out[row*3+2] = r1[0];
}

// ---------------- host launcher ----------------
extern "C" void kernel_launch(void* const* d_in, const int* in_sizes, int n_in,
                              void* d_out, int out_size) {
    (void)in_sizes; (void)n_in; (void)out_size;
    const float* a    = (const float*)d_in[0];
    const float* qin  = (const float*)d_in[1];
    const float* c    = (const float*)d_in[2];
    const float* bias = (const float*)d_in[3];
    const float* a2t  = (const float*)d_in[4];
    const float* mask = (const float*)d_in[5];
    const int*   kidx = (const int*)  d_in[6];
    const float* a2q  = (const float*)d_in[7];
    const float* Wq   = (const float*)d_in[8];
    const float* Wk   = (const float*)d_in[9];
    const float* Wv   = (const float*)d_in[10];
    const float* Wg   = (const float*)d_in[11];
    const float* Wo   = (const float*)d_in[12];
    const float* Wcs  = (const float*)d_in[13];
    const float* Wcb  = (const float*)d_in[14];
    const float* Wog  = (const float*)d_in[15];
    const float* Wcs2 = (const float*)d_in[16];
    const float* Wcb2 = (const float*)d_in[17];
    const float* Wog2 = (const float*)d_in[18];
    const float* W1   = (const float*)d_in[19];
    const float* W2   = (const float*)d_in[20];
    const float* W3   = (const float*)d_in[21];
    const float* ln_g = (const float*)d_in[22];
    const float* ln_b = (const float*)d_in[23];
    const float* Wpos = (const float*)d_in[24];
    const float* Wres = (const float*)d_in[25];
    const float* bres = (const float*)d_in[26];
    float* out = (float*)d_out;

    float *pq, *pt1, *pt2, *pkv, *pcng, *paw, *psf;
    __half *pcn, *ph, *pt3, *pwp;
    int *ptok;
    cudaGetSymbolAddress((void**)&pq,   g_q);
    cudaGetSymbolAddress((void**)&pcn,  g_cn);
    cudaGetSymbolAddress((void**)&ph,   g_h);
    cudaGetSymbolAddress((void**)&pt1,  g_t1);
    cudaGetSymbolAddress((void**)&pt2,  g_t2);
    cudaGetSymbolAddress((void**)&pt3,  g_t3);
    cudaGetSymbolAddress((void**)&pkv,  g_kv);
    cudaGetSymbolAddress((void**)&pcng, g_cng);
    cudaGetSymbolAddress((void**)&paw,  g_aw);
    cudaGetSymbolAddress((void**)&psf,  g_sf);
    cudaGetSymbolAddress((void**)&pwp,  g_wp);
    cudaGetSymbolAddress((void**)&ptok, g_tok);

    cudaFuncSetAttribute(gemm_tc, cudaFuncAttributeMaxDynamicSharedMemorySize, GEMM_SMEM);

    __half* acvt = (__half*)pcng;     // prologue-only fp16 view
    __half* pglu = (__half*)pt1;      // glu out (rows of 512 halves)

    // prologue
    pack_all<<<512, 256>>>(Wcs, Wcb, Wog, Wcs2, Wcb2, Wog2, Wq, Wg, Wk, Wv,
                           W1, W2, Wo, W3, a2q, pwp);
    argmax_tok<<<BN/8, 256>>>(a2t, ptok);
    cvt_hilo<<<(Bb*Tt*Ss/4 + 255)/256, 256>>>(a, acvt, Ss, Bb*Tt*Ss/4);
    gemm_tc<<<dim3(1, (Bb*Tt)/128), 256, GEMM_SMEM>>>(acvt, pwp + (size_t)Ll*PL1,
        paw, 128, Ss);
    addaw_kernel<<<(BN*32)/256, 256>>>(qin, paw, ptok, pq);
    ln_rows<<<BN/8, 256>>>(c, pcn);

    for (int l = 0; l < Ll; l++) {
        __half* wl = pwp + (size_t)l*PL1;
        // all six cn projections: [cs|cb|og|cs2|cb2|og2]
        gemm_tc<<<dim3(6, BN/128), 256, GEMM_SMEM>>>(pcn, wl, pcng, 768, Dd);
        // hcur = ln(q)*sig(cs) + cb  -> fp16 hi|lo
        ew_hcur<<<BN/8, 256>>>(pq, pcng, 768, ph);
        // fused Q|G|K|V projection
        gemm_tc<<<dim3(4, BN/128), 256, GEMM_SMEM>>>(ph, wl + 98304, pt2, 512, Dd);
        // attention (gathers K/V via kidx, sigmoid(G) gate) -> fp16 hi|lo
        attn_kernel<<<dim3(NHh, NWw, Bb), 128>>>(pt2, bias, mask, kidx, pt3);
        // q += sig(og) * (o@Wo)
        gemm_tc<<<dim3(1, BN/128), 256, GEMM_SMEM>>>(pt3, wl + 229376, pt1, 128, Dd);
        ew_resid<<<(BN*32)/256, 256>>>(pq, pcng + 256, 768, pt1);
        // h2 = ln(q)*sig(cs2) + cb2 -> fp16 hi|lo
        ew_hcur<<<BN/8, 256>>>(pq, pcng + 384, 768, ph);
        // FFN
        gemm_tc<<<dim3(4, BN/128), 256, GEMM_SMEM>>>(ph, wl + 163840, pkv, 512, Dd);
        ew_glu<<<(BN*64)/256, 256>>>(pkv, pglu);
        gemm_tc<<<dim3(1, BN/128), 256, GEMM_SMEM>>>(pglu, wl + 245760, pt2, 128, 256);
        ew_resid<<<(BN*32)/256, 256>>>(pq, pcng + 640, 768, pt2);
    }

    // epilogue
    cudaMemsetAsync(psf, 0, (size_t)Bb*Tt*Dd*sizeof(float));
    sfeat_kernel<<<(BN*128)/256, 256>>>(pq, mask, ptok, psf);
    restype_kernel<<<Bb*Tt, 128>>>(psf, Wres, bres, out + (size_t)BN*3);
    rupdate_kernel<<<BN, 128>>>(pq, ln_g, ln_b, Wpos, out);
}